// round 13
// baseline (speedup 1.0000x reference)
#include <cuda_runtime.h>

// LIF neuron group, T=1000 serial steps x 65536 neurons. Pure HBM stream
// (512 MB read + 256 MB write, irreducible). Champion structure (R6/R12):
// float2 lanes, one-warp blocks, quint rotating register buffers x STAGES=8
// (loads 4 blocks ahead, ~17 MB chip-wide in flight), .cg loads, .cs stores
// (both cache-policy axes fully mapped R9-R11).
// R13: kill the residual wave imbalance. 1024 blocks on 148 SMs = 12 SMs
// with 6 blocks finishing 1/7 early (~1.2% lost capacity, mechanism proven
// in R4). Fix: 1036 blocks = exactly 7/SM; 652 blocks own 32 float2 lanes,
// 384 own 31 (652*32+384*31 = 32768). Equal per-block runtime -> perfect
// balance. Inactive lane (1 per warp in the 31-lane blocks) clamps its load
// index (dup load, L2 hit) and predicates off its stores.

#define NUM_NEURONS 65536
#define T_STEPS     1000
#define NVEC        (NUM_NEURONS / 2)     // 32768 float2 lanes
#define THREADS     32                    // 1 warp per block
#define BLOCKS      1036                  // 148 SMs x 7 blocks exactly
#define FULL_BLOCKS 652                   // blocks with 32 lanes (rest: 31)
#define STAGES      8                     // timesteps per pipeline block (125 blocks)

__device__ __forceinline__ float2 lif_step(const float2 i2, const float2 n2,
                                           float2& V, float2& th)
{
    const float decay = 0.05f, eta = 0.1f, nstd = 0.1f;
    const float thmin = 0.5f, thmax = 2.0f;
    float2 s;
#define LIF_C(c)                                                     \
    {                                                                \
        float ie = fmaf(nstd, n2.c, i2.c);                           \
        float v  = fmaf(decay, ie - V.c, V.c);                       \
        bool  sp = (v >= th.c);                                      \
        s.c  = sp ? 1.0f : 0.0f;                                     \
        V.c  = sp ? 0.0f : v;                                        \
        th.c = fminf(fmaxf(fmaf(eta, s.c, th.c), thmin), thmax);     \
    }
    LIF_C(x) LIF_C(y)
#undef LIF_C
    return s;
}

__global__ __launch_bounds__(THREADS, 7)
void lif_kernel(const float2* __restrict__ icur,
                const float2* __restrict__ nz,
                float2* __restrict__ out)
{
    const int b    = blockIdx.x;
    const int lane = threadIdx.x;

    // Lane ranges: blocks [0,652) own 32 lanes, blocks [652,1036) own 31.
    const int  base  = (b < FULL_BLOCKS) ? (b * 32)
                                         : (FULL_BLOCKS * 32 + (b - FULL_BLOCKS) * 31);
    const int  lanes = (b < FULL_BLOCKS) ? 32 : 31;
    const bool act   = (lane < lanes);
    const int  idx   = base + (act ? lane : 0);   // inactive lane: dup of lane 0

    const float2* ip = icur + idx;
    const float2* np = nz   + idx;
    float2*       op = out  + idx;

    float2 V  = make_float2(0.0f, 0.0f);
    float2 th = make_float2(1.0f, 1.0f);

    float2 AI[STAGES], AN[STAGES];
    float2 BI[STAGES], BN[STAGES];
    float2 CI[STAGES], CN[STAGES];
    float2 DI[STAGES], DN[STAGES];
    float2 EI[STAGES], EN[STAGES];

    // blk k covers timesteps [k*STAGES, (k+1)*STAGES)
#define LOAD_BLK(I_, N_, k)                                           \
    _Pragma("unroll")                                                 \
    for (int j = 0; j < STAGES; j++) {                                \
        I_[j] = __ldcg(ip + (size_t)((k) * STAGES + j) * NVEC);       \
        N_[j] = __ldcg(np + (size_t)((k) * STAGES + j) * NVEC);      \
    }

#define COMP_BLK(I_, N_, k)                                           \
    _Pragma("unroll")                                                 \
    for (int j = 0; j < STAGES; j++) {                                \
        float2 s = lif_step(I_[j], N_[j], V, th);                     \
        if (act) __stcs(op + (size_t)((k) * STAGES + j) * NVEC, s);   \
    }

    // 125 blocks of 8. Quint buffer: loads run 4 blocks ahead of compute.
    LOAD_BLK(AI, AN, 0)
    LOAD_BLK(BI, BN, 1)
    LOAD_BLK(CI, CN, 2)
    LOAD_BLK(DI, DN, 3)

    for (int p = 0; p < 24; p++) {
        const int k = 5 * p;                                 // 0,5,...,115
        LOAD_BLK(EI, EN, k + 4)   COMP_BLK(AI, AN, k)        // load <= 119
        LOAD_BLK(AI, AN, k + 5)   COMP_BLK(BI, BN, k + 1)    // load <= 120
        LOAD_BLK(BI, BN, k + 6)   COMP_BLK(CI, CN, k + 2)    // load <= 121
        LOAD_BLK(CI, CN, k + 7)   COMP_BLK(DI, DN, k + 3)    // load <= 122
        LOAD_BLK(DI, DN, k + 8)   COMP_BLK(EI, EN, k + 4)    // load <= 123
    }
    // computed 0..119; A=120, B=121, C=122, D=123
    LOAD_BLK(EI, EN, 124)   COMP_BLK(AI, AN, 120)
    COMP_BLK(BI, BN, 121)
    COMP_BLK(CI, CN, 122)
    COMP_BLK(DI, DN, 123)
    COMP_BLK(EI, EN, 124)

#undef LOAD_BLK
#undef COMP_BLK
}

extern "C" void kernel_launch(void* const* d_in, const int* in_sizes, int n_in,
                              void* d_out, int out_size)
{
    const float2* icur = (const float2*)d_in[0];   // input_current (T, N) f32
    const float2* nz   = (const float2*)d_in[1];   // noise         (T, N) f32
    float2*       out  = (float2*)d_out;           // spikes        (T, N) f32

    lif_kernel<<<BLOCKS, THREADS>>>(icur, nz, out);
}

// round 14
// speedup vs baseline: 1.0131x; 1.0131x over previous
#include <cuda_runtime.h>

// ============================================================================
// FINAL — LIF neuron group, T=1000 serial steps x 65536 neurons.
//
// Pure HBM stream: 512 MB read + 256 MB write, zero reuse, irreducible.
// ncu: ~112us kernel x 6.65 TB/s == exactly 768 MB -> byte-floor-bound at
// the mixed 2:1 R/W DRAM-turnaround plateau (83-84% bus-active).
//
// Optimization history (single-variable, theory-first, 13 rounds):
//   R1  naive float4 streaming, 16K thr          587us  (DRAM 16%, latency-bound)
//   R2  A/B register pipeline (8 steps/blk)      154us  (DRAM 64%)
//   R3  float2 lanes, 2x warps                   145us  (DRAM 67%)
//   R4  1024 one-warp blocks (7-vs-6/SM), 3buf   130us  (DRAM 75%)
//   R5  quad buffer + launch_bounds(32,7)        117us  (DRAM 83%)
//   R6  quint buffer                             117us  (depth saturated)
//   R7  scalar lanes / 2x warps                  FALSIFIED (-3.1pts DRAM)
//   R8  STAGES=5 x 8buf (finer bursts)           tie
//   R9  write-back stores                        FALSIFIED (-3.5pts)
//   R10 write-through stores                     FALSIFIED (-2.3pts)
//   R11 .cg loads (L1 bypass)                    exact tie (kept)
//   R13 perfect wave balance via 31-lane blocks  FALSIFIED (misalignment
//       sector overhead > 1.2% imbalance tail)
// ============================================================================

#define NUM_NEURONS 65536
#define T_STEPS     1000
#define NVEC        (NUM_NEURONS / 2)     // 32768 float2 lanes
#define THREADS     32                    // 1 warp per block
#define BLOCKS      (NVEC / THREADS)      // 1024 blocks -> 7 vs 6 per SM
#define STAGES      8                     // timesteps per pipeline block (125 blocks)

__device__ __forceinline__ float2 lif_step(const float2 i2, const float2 n2,
                                           float2& V, float2& th)
{
    const float decay = 0.05f, eta = 0.1f, nstd = 0.1f;
    const float thmin = 0.5f, thmax = 2.0f;
    float2 s;
#define LIF_C(c)                                                     \
    {                                                                \
        float ie = fmaf(nstd, n2.c, i2.c);                           \
        float v  = fmaf(decay, ie - V.c, V.c);                       \
        bool  sp = (v >= th.c);                                      \
        s.c  = sp ? 1.0f : 0.0f;                                     \
        V.c  = sp ? 0.0f : v;                                        \
        th.c = fminf(fmaxf(fmaf(eta, s.c, th.c), thmin), thmax);     \
    }
    LIF_C(x) LIF_C(y)
#undef LIF_C
    return s;
}

__global__ __launch_bounds__(THREADS, 7)
void lif_kernel(const float2* __restrict__ icur,
                const float2* __restrict__ nz,
                float2* __restrict__ out)
{
    const int idx = blockIdx.x * THREADS + threadIdx.x;   // 0 .. NVEC-1

    const float2* ip = icur + idx;
    const float2* np = nz   + idx;
    float2*       op = out  + idx;

    float2 V  = make_float2(0.0f, 0.0f);
    float2 th = make_float2(1.0f, 1.0f);

    float2 AI[STAGES], AN[STAGES];
    float2 BI[STAGES], BN[STAGES];
    float2 CI[STAGES], CN[STAGES];
    float2 DI[STAGES], DN[STAGES];
    float2 EI[STAGES], EN[STAGES];

    // blk b covers timesteps [b*STAGES, (b+1)*STAGES)
#define LOAD_BLK(I_, N_, b)                                           \
    _Pragma("unroll")                                                 \
    for (int j = 0; j < STAGES; j++) {                                \
        I_[j] = __ldcg(ip + (size_t)((b) * STAGES + j) * NVEC);       \
        N_[j] = __ldcg(np + (size_t)((b) * STAGES + j) * NVEC);      \
    }

#define COMP_BLK(I_, N_, b)                                           \
    _Pragma("unroll")                                                 \
    for (int j = 0; j < STAGES; j++) {                                \
        float2 s = lif_step(I_[j], N_[j], V, th);                     \
        __stcs(op + (size_t)((b) * STAGES + j) * NVEC, s);            \
    }

    // 125 blocks of 8. Quint buffer: loads run 4 blocks ahead of compute.
    LOAD_BLK(AI, AN, 0)
    LOAD_BLK(BI, BN, 1)
    LOAD_BLK(CI, CN, 2)
    LOAD_BLK(DI, DN, 3)

    for (int p = 0; p < 24; p++) {
        const int b = 5 * p;                                 // 0,5,...,115
        LOAD_BLK(EI, EN, b + 4)   COMP_BLK(AI, AN, b)        // load <= 119
        LOAD_BLK(AI, AN, b + 5)   COMP_BLK(BI, BN, b + 1)    // load <= 120
        LOAD_BLK(BI, BN, b + 6)   COMP_BLK(CI, CN, b + 2)    // load <= 121
        LOAD_BLK(CI, CN, b + 7)   COMP_BLK(DI, DN, b + 3)    // load <= 122
        LOAD_BLK(DI, DN, b + 8)   COMP_BLK(EI, EN, b + 4)    // load <= 123
    }
    // computed 0..119; A=120, B=121, C=122, D=123
    LOAD_BLK(EI, EN, 124)   COMP_BLK(AI, AN, 120)
    COMP_BLK(BI, BN, 121)
    COMP_BLK(CI, CN, 122)
    COMP_BLK(DI, DN, 123)
    COMP_BLK(EI, EN, 124)

#undef LOAD_BLK
#undef COMP_BLK
}

extern "C" void kernel_launch(void* const* d_in, const int* in_sizes, int n_in,
                              void* d_out, int out_size)
{
    const float2* icur = (const float2*)d_in[0];   // input_current (T, N) f32
    const float2* nz   = (const float2*)d_in[1];   // noise         (T, N) f32
    float2*       out  = (float2*)d_out;           // spikes        (T, N) f32

    lif_kernel<<<BLOCKS, THREADS>>>(icur, nz, out);
}